// round 9
// baseline (speedup 1.0000x reference)
#include <cuda_runtime.h>
#include <cstdint>
#include <cstddef>

#define NB   1024
#define NC   8
#define NT   32
#define NE   128
#define NH   256
#define SEG  64
#define SIG  1056

// ---------------- device scratch (static; no allocations) ----------------
__device__ __align__(16) float g_W1p[8 * 16 * 32 * 8];     // 32768 tf32, GEMM1-B frag pack
__device__ __align__(16) float g_W2T[NH * SEG];            // [h][s] = (Winv@W2)^T
__device__ __align__(16) float g_W2p[4 * 8 * 2 * 32 * 8];  // 16384 tf32, GEMM2-B frag pack (K4)
__device__ __align__(16) float g_b2i[SEG];                 // binv + Winv@b2

// ---------------- helpers ----------------
__device__ __forceinline__ uint32_t f2tf32(float x) {
    uint32_t u;
    asm("cvt.rna.tf32.f32 %0, %1;" : "=r"(u) : "f"(x));
    return u;
}

__device__ __forceinline__ void cpasync16(uint32_t saddr, const void* gaddr) {
    asm volatile("cp.async.cg.shared.global [%0], [%1], 16;" :: "r"(saddr), "l"(gaddr));
}
#define CPASYNC_COMMIT() asm volatile("cp.async.commit_group;")
#define CPASYNC_WAIT0()  asm volatile("cp.async.wait_group 0;")

#define MMA_TF32(C, A, b0v, b1v)                                               \
    asm volatile(                                                              \
        "mma.sync.aligned.m16n8k8.row.col.f32.tf32.tf32.f32 "                  \
        "{%0,%1,%2,%3},{%4,%5,%6,%7},{%8,%9},{%0,%1,%2,%3};"                   \
        : "+f"((C)[0]), "+f"((C)[1]), "+f"((C)[2]), "+f"((C)[3])               \
        : "r"((A)[0]), "r"((A)[1]), "r"((A)[2]), "r"((A)[3]),                  \
          "r"(b0v), "r"(b1v))

// ---------------- prep kernels ----------------
__global__ void zero_out(float* __restrict__ out) {
    out[blockIdx.x * 256 + threadIdx.x] = 0.f;     // 4224 * 256 = 1024*1056
}

// W1 [j=256][k=128] -> GEMM1-B frag pack:
// g_W1p[((w*16+ks)*32+l)*8 + v]; v = nt*2+hh; value = W1[32w+8nt+g][8ks+tg+4hh]
__global__ void prep_w1p(const float* __restrict__ W1) {
    int id = blockIdx.x * 256 + threadIdx.x;     // 32768
    int v  = id & 7;
    int l  = (id >> 3) & 31;
    int ks = (id >> 8) & 15;
    int w  = id >> 12;
    int g = l >> 2, tg = l & 3, nt = v >> 1, hh = v & 1;
    int j = 32 * w + 8 * nt + g;
    int k = 8 * ks + tg + 4 * hh;
    ((uint32_t*)g_W1p)[id] = f2tf32(W1[j * NE + k]);
}

// W2T[h][s] = sum_e Winv[s][e]*W2[e][h];  b2i[s] = binv[s] + Winv[s]·b2
__global__ void prep_w2(const float* __restrict__ W2, const float* __restrict__ Winv,
                        const float* __restrict__ b2, const float* __restrict__ binv) {
    int s = blockIdx.x;        // 64
    int h = threadIdx.x;       // 256
    const float* wr = Winv + s * NE;
    float acc = 0.f;
    #pragma unroll 4
    for (int e = 0; e < NE; ++e) acc += wr[e] * W2[e * NH + h];
    g_W2T[h * SEG + s] = acc;
    if (h == 0) {
        float t = 0.f;
        for (int e = 0; e < NE; ++e) t += wr[e] * b2[e];
        g_b2i[s] = binv[s] + t;
    }
}

// W2T -> GEMM2-B frag pack (K-split 4, s-split 2, n32 warp tiles):
// g_W2p[(((kq*8+ksl)*2+sh)*32+l)*8 + comp]; comp = nt2*2+hh
// value = W2T[h=8*(kq*8+ksl)+tg+4hh][s=32sh+8nt2+g]
__global__ void prep_w2p() {
    int id   = blockIdx.x * 256 + threadIdx.x;   // 16384
    int comp = id & 7;
    int l    = (id >> 3) & 31;
    int sh   = (id >> 8) & 1;
    int ksl  = (id >> 9) & 7;
    int kq   = (id >> 12) & 3;
    int g = l >> 2, tg = l & 3;
    int nt2 = comp >> 1, hh = comp & 1;
    int h = 8 * (kq * 8 + ksl) + tg + 4 * hh;
    int s = 32 * sh + 8 * nt2 + g;
    ((uint32_t*)g_W2p)[id] = f2tf32(g_W2T[h * SEG + s]);
}

// ---------------- main kernel ----------------
// smem float offsets (~104.5 KB -> 2 CTAs/SM)
#define OFF_ENC  0        // 8448   2 enc tiles [32][132] (raw fp32)
#define OFF_HA   8448     // 8192   hA (tf32 bits, frag order, XOR-swizzled rows)
#define OFF_SEG  16640    // 8704   4 partial seg [32][68]
#define OFF_SIG  25344    // 1058
#define OFF_B1   26402    // 256
#define OFF_B2   26658    // 64
#define OFF_WCV  26722    // 24
#define SMEM_FLOATS 26752
#define SMEM_BYTES  (SMEM_FLOATS * 4)

__device__ __forceinline__ float cinvf(int p) {
    return (p < 32 || p >= 1024) ? 1.0f : 0.5f;   // 1/overlap-count
}

__global__ __launch_bounds__(256, 2)
void decoder_main(const float* __restrict__ enc, const float* __restrict__ b1,
                  const float* __restrict__ Wconv, const float* __restrict__ bconv,
                  float* __restrict__ out) {
    extern __shared__ float sm[];
    uint32_t* encU = (uint32_t*)(sm + OFF_ENC);
    uint32_t* hAU  = (uint32_t*)(sm + OFF_HA);
    float*    segB = sm + OFF_SEG;
    float*    sig  = sm + OFF_SIG;
    float*    b1s  = sm + OFF_B1;
    float*    b2s  = sm + OFF_B2;
    float*    wcv  = sm + OFF_WCV;
    const uint32_t smemBase = (uint32_t)__cvta_generic_to_shared(sm);

    const int tid  = threadIdx.x;
    const int l    = tid & 31;
    const int w    = tid >> 5;      // warp 0..7
    const int g    = l >> 2;
    const int tg   = l & 3;
    const int b    = blockIdx.x >> 1;
    const int half = blockIdx.x & 1;   // which 4 channels this CTA handles
    const int kq   = w >> 1;        // GEMM2 K-quarter
    const int sh   = w & 1;         // GEMM2 s-half
    const int lsw  = l ^ ((l >> 3) & 7);  // swizzled chunk index for GEMM2 A reads

    b1s[tid] = b1[tid];
    if (tid < SEG) b2s[tid] = g_b2i[tid];
    if (tid < 24)  wcv[tid] = Wconv[tid];
    if (tid == 0) { sig[0] = 0.f; sig[1057] = 0.f; }

    float oa[5];                    // out partial accumulator: p = tid + 256*i
    #pragma unroll
    for (int i = 0; i < 5; ++i) oa[i] = 0.f;

    const int cp0 = 2 * half;       // this CTA's channel pairs: cp0, cp0+1

    // ---- prologue: stage first enc pair via cp.async (raw fp32, stride 132) ----
    #pragma unroll
    for (int ch = 0; ch < 2; ++ch) {
        const float* src = enc + (size_t)(b * NC + 2 * cp0 + ch) * (NT * NE);
        #pragma unroll
        for (int r = 0; r < 4; ++r) {
            int fi = tid + 256 * r;
            int m = fi >> 5, kk = fi & 31;
            cpasync16(smemBase + (uint32_t)(OFF_ENC + ch * 4224 + m * 132 + kk * 4) * 4,
                      src + fi * 4);
        }
    }
    CPASYNC_COMMIT();

    for (int cpi = 0; cpi < 2; ++cpi) {
        const int cp = cp0 + cpi;
        CPASYNC_WAIT0();
        __syncthreads();

        // ---- GEMM1 both channels, B loaded once per pair ----
        float c1[2][2][4][4];                       // [ch][mt][nt][4]
        #pragma unroll
        for (int nt = 0; nt < 4; ++nt) {
            float bb0 = b1s[32 * w + 8 * nt + 2 * tg];
            float bb1 = b1s[32 * w + 8 * nt + 2 * tg + 1];
            #pragma unroll
            for (int ch = 0; ch < 2; ++ch)
                #pragma unroll
                for (int mt = 0; mt < 2; ++mt) {
                    c1[ch][mt][nt][0] = bb0; c1[ch][mt][nt][1] = bb1;
                    c1[ch][mt][nt][2] = bb0; c1[ch][mt][nt][3] = bb1;
                }
        }
        {
            const uint4* W1g = (const uint4*)g_W1p;
            int bidx = w * 1024 + l * 2;
            uint4 B0 = __ldg(&W1g[bidx]);
            uint4 B1 = __ldg(&W1g[bidx + 1]);
            #pragma unroll
            for (int ks = 0; ks < 16; ++ks) {
                uint4 nB0, nB1;
                if (ks < 15) {
                    nB0 = __ldg(&W1g[bidx + 64 * (ks + 1)]);
                    nB1 = __ldg(&W1g[bidx + 64 * (ks + 1) + 1]);
                }
                #pragma unroll
                for (int ch = 0; ch < 2; ++ch) {
                    const uint32_t* eU = encU + ch * 4224;
                    #pragma unroll
                    for (int mt = 0; mt < 2; ++mt) {
                        uint32_t a[4];
                        int r0 = (mt * 16 + g) * 132;
                        int k0 = 8 * ks + tg;
                        a[0] = eU[r0 + k0];
                        a[1] = eU[r0 + 8 * 132 + k0];
                        a[2] = eU[r0 + k0 + 4];
                        a[3] = eU[r0 + 8 * 132 + k0 + 4];
                        MMA_TF32(c1[ch][mt][0], a, B0.x, B0.y);
                        MMA_TF32(c1[ch][mt][1], a, B0.z, B0.w);
                        MMA_TF32(c1[ch][mt][2], a, B1.x, B1.y);
                        MMA_TF32(c1[ch][mt][3], a, B1.z, B1.w);
                    }
                }
                B0 = nB0; B1 = nB1;
            }
        }
        __syncthreads();   // all warps done reading enc

        // ---- prefetch next enc pair (overlaps epilogue/GEMM2/conv below) ----
        if (cpi < 1) {
            #pragma unroll
            for (int ch = 0; ch < 2; ++ch) {
                const float* src =
                    enc + (size_t)(b * NC + 2 * (cp + 1) + ch) * (NT * NE);
                #pragma unroll
                for (int r = 0; r < 4; ++r) {
                    int fi = tid + 256 * r;
                    int m = fi >> 5, kk = fi & 31;
                    cpasync16(smemBase +
                              (uint32_t)(OFF_ENC + ch * 4224 + m * 132 + kk * 4) * 4,
                              src + fi * 4);
                }
            }
            CPASYNC_COMMIT();
        }

        for (int sub = 0; sub < 2; ++sub) {
            // ---- epilogue: ReLU + tf32 + swizzled scatter ----
            {
                int col0 = 2 * tg, col1 = 2 * tg + 1;
                int i00 = (4 * g + (col0 & 3)) * 4 + 2 * (col0 >= 4);
                int i01 = (4 * g + (col1 & 3)) * 4 + 2 * (col1 >= 4);
                int c00 = i00 >> 2, c01 = i01 >> 2;
                int j00 = ((c00 ^ ((c00 >> 3) & 7)) << 2) + (i00 & 3);
                int j01 = ((c01 ^ ((c01 >> 3) & 7)) << 2) + (i01 & 3);
                #pragma unroll
                for (int mt = 0; mt < 2; ++mt)
                    #pragma unroll
                    for (int nt = 0; nt < 4; ++nt) {
                        uint32_t* bp = hAU + (mt * 32 + (4 * w + nt)) * 128;
                        uint2 u0, u1;
                        u0.x = f2tf32(fmaxf(c1[sub][mt][nt][0], 0.f));
                        u0.y = f2tf32(fmaxf(c1[sub][mt][nt][2], 0.f));
                        u1.x = f2tf32(fmaxf(c1[sub][mt][nt][1], 0.f));
                        u1.y = f2tf32(fmaxf(c1[sub][mt][nt][3], 0.f));
                        *(uint2*)(bp + j00) = u0;
                        *(uint2*)(bp + j01) = u1;
                    }
            }
            __syncthreads();

            // ---- GEMM2: K-split 4, s-split 2, n32 per warp (swizzled A reads) ----
            {
                const uint4* hU4 = (const uint4*)hAU;
                const uint4* W2g = (const uint4*)g_W2p;
                float c2[2][4][4];                  // [mt][nt2][4]
                #pragma unroll
                for (int nt2 = 0; nt2 < 4; ++nt2) {
                    float bb0 = (kq == 0) ? b2s[32 * sh + 8 * nt2 + 2 * tg] : 0.f;
                    float bb1 = (kq == 0) ? b2s[32 * sh + 8 * nt2 + 2 * tg + 1] : 0.f;
                    #pragma unroll
                    for (int mt = 0; mt < 2; ++mt) {
                        c2[mt][nt2][0] = bb0; c2[mt][nt2][1] = bb1;
                        c2[mt][nt2][2] = bb0; c2[mt][nt2][3] = bb1;
                    }
                }
                int b2idx = (((kq * 8) * 2 + sh) * 32 + l) * 2;
                uint4 Bv0 = __ldg(&W2g[b2idx]);
                uint4 Bv1 = __ldg(&W2g[b2idx + 1]);
                #pragma unroll
                for (int ksl = 0; ksl < 8; ++ksl) {
                    uint4 nBv0, nBv1;
                    if (ksl < 7) {
                        nBv0 = __ldg(&W2g[b2idx + 128 * (ksl + 1)]);
                        nBv1 = __ldg(&W2g[b2idx + 128 * (ksl + 1) + 1]);
                    }
                    int ks2 = kq * 8 + ksl;
                    uint4 A0 = hU4[(0 * 32 + ks2) * 32 + lsw];
                    uint4 A1 = hU4[(1 * 32 + ks2) * 32 + lsw];
                    MMA_TF32(c2[0][0], (&A0.x), Bv0.x, Bv0.y);
                    MMA_TF32(c2[0][1], (&A0.x), Bv0.z, Bv0.w);
                    MMA_TF32(c2[0][2], (&A0.x), Bv1.x, Bv1.y);
                    MMA_TF32(c2[0][3], (&A0.x), Bv1.z, Bv1.w);
                    MMA_TF32(c2[1][0], (&A1.x), Bv0.x, Bv0.y);
                    MMA_TF32(c2[1][1], (&A1.x), Bv0.z, Bv0.w);
                    MMA_TF32(c2[1][2], (&A1.x), Bv1.x, Bv1.y);
                    MMA_TF32(c2[1][3], (&A1.x), Bv1.z, Bv1.w);
                    Bv0 = nBv0; Bv1 = nBv1;
                }

                // ---- store partial seg (kq -> its own buffer, no RMW) ----
                float* sp = segB + kq * 2176;
                #pragma unroll
                for (int mt = 0; mt < 2; ++mt)
                    #pragma unroll
                    for (int nt2 = 0; nt2 < 4; ++nt2) {
                        int s0 = 32 * sh + 8 * nt2 + 2 * tg;
                        float2 v0 = make_float2(c2[mt][nt2][0], c2[mt][nt2][1]);
                        float2 v1 = make_float2(c2[mt][nt2][2], c2[mt][nt2][3]);
                        *(float2*)&sp[(mt * 16 + g) * 68 + s0]     = v0;
                        *(float2*)&sp[(mt * 16 + g + 8) * 68 + s0] = v1;
                    }
            }
            __syncthreads();

            // ---- overlap-add + normalize -> sig (conflict-free linear) ----
            for (int p = tid; p < SIG; p += 256) {
                int t = p >> 5, s = p & 31;
                float v = 0.f;
                #pragma unroll
                for (int q = 0; q < 4; ++q) {
                    const float* sp = segB + q * 2176;
                    if (t < 32) v += sp[t * 68 + s];
                    if (t > 0)  v += sp[(t - 1) * 68 + s + 32];
                }
                sig[1 + p] = v * cinvf(p);
            }
            __syncthreads();

            // ---- conv tap for this channel -> oa regs ----
            {
                int c = 2 * cp + sub;
                float w0c = wcv[c * 3 + 0];
                float w1c = wcv[c * 3 + 1];
                float w2c = wcv[c * 3 + 2];
                #pragma unroll
                for (int i = 0; i < 5; ++i) {
                    int p = tid + 256 * i;
                    if (p < SIG)
                        oa[i] += w0c * sig[p] + w1c * sig[p + 1] + w2c * sig[p + 2];
                }
            }
            __syncthreads();   // sig consumed; hA/seg reusable next sub
        }
    }

    // ---- reduce the two half-CTAs into zero-initialized out ----
    float bc = (half == 0) ? bconv[0] : 0.f;
    #pragma unroll
    for (int i = 0; i < 5; ++i) {
        int p = tid + 256 * i;
        if (p < SIG) atomicAdd(&out[(size_t)b * SIG + p], oa[i] + bc);
    }
}

// ---------------- launch ----------------
extern "C" void kernel_launch(void* const* d_in, const int* in_sizes, int n_in,
                              void* d_out, int out_size) {
    (void)in_sizes; (void)n_in; (void)out_size;
    const float* enc   = (const float*)d_in[0];
    const float* W1    = (const float*)d_in[1];
    const float* b1    = (const float*)d_in[2];
    const float* W2    = (const float*)d_in[3];
    const float* b2    = (const float*)d_in[4];
    const float* Winv  = (const float*)d_in[5];
    const float* binv  = (const float*)d_in[6];
    const float* Wconv = (const float*)d_in[7];
    const float* bconv = (const float*)d_in[8];
    float* out = (float*)d_out;

    cudaFuncSetAttribute(decoder_main, cudaFuncAttributeMaxDynamicSharedMemorySize,
                         SMEM_BYTES);

    zero_out<<<4224, 256>>>(out);
    prep_w1p<<<128, 256>>>(W1);
    prep_w2<<<64, 256>>>(W2, Winv, b2, binv);
    prep_w2p<<<64, 256>>>();
    decoder_main<<<2 * NB, 256, SMEM_BYTES>>>(enc, b1, Wconv, bconv, out);
}